// round 14
// baseline (speedup 1.0000x reference)
#include <cuda_runtime.h>
#include <cuda_fp16.h>

// RoIAlign: r10 float2 transpose + champion gather with balanced 7-warp bins.
// feat: (B=2, C=256, H=200, W=336) fp32 NCHW
// rois: (N=1000, 5) [bidx, x1, y1, x2, y2] fp32
// out:  (N, 256, 7, 7) fp32

#define B_    2
#define C_    256
#define H_    200
#define W_    336
#define OUTH  7
#define OUTW  7
#define NBIN  49
#define HWC   (H_ * W_ * C_)
#define CHALF 128
#define GTHREADS 224   // 7 warps -> 7 bins each, perfectly balanced

// NHWC fp16 scratch: [B][H][W][C]
__device__ __half g_feat16[(size_t)B_ * HWC];

// ---------------------------------------------------------------------------
// Kernel 1: NCHW fp32 -> NHWC fp16. Block: 64 channels x 64 x-positions,
// float2 reads. smem pad 65 (odd) keeps write-phase LDS at 2-way conflict.
// ---------------------------------------------------------------------------
__global__ __launch_bounds__(256) void transpose_kernel(const float* __restrict__ feat)
{
    __shared__ float tile[64][65];   // [c][x]

    int xt = blockIdx.x * 64;
    int by = blockIdx.y;             // b*H + y
    int b  = by / H_;
    int y  = by % H_;
    int c0 = blockIdx.z * 64;
    int tx = threadIdx.x;
    int ty = threadIdx.y;

    const float* src = feat + ((size_t)(b * C_ + c0) * H_ + y) * W_;
    int  x2  = xt + 2 * tx;          // even
    bool xin = x2 < W_;              // W even -> covers x2+1 too

    #pragma unroll
    for (int k = 0; k < 8; k++) {
        int c = ty + k * 8;
        float2 v = make_float2(0.f, 0.f);
        if (xin) v = *(const float2*)(src + (size_t)c * (H_ * W_) + x2);
        tile[c][2 * tx]     = v.x;
        tile[c][2 * tx + 1] = v.y;
    }
    __syncthreads();

    __half* dst = g_feat16 + ((size_t)(b * H_ + y) * W_) * C_ + c0;
    #pragma unroll
    for (int k = 0; k < 8; k++) {
        int xl = ty + k * 8;
        int x  = xt + xl;
        if (x < W_) {
            __half2 v = __floats2half2_rn(tile[2 * tx][xl], tile[2 * tx + 1][xl]);
            *(__half2*)(dst + (size_t)x * C_ + 2 * tx) = v;
        }
    }
}

// ---------------------------------------------------------------------------
// Kernel 2: gather. grid (N, 2): roi x channel-half. 224 threads = 7 warps.
// Warp w handles bins w, w+7, ..., w+42 -> exactly 7 bins per warp.
// Lane covers 4 channels (uint2) -> each corner is one contiguous 256B warp
// request. All 16 loads front-batched (MLP=16). Fused smem tables.
// ---------------------------------------------------------------------------
__global__ __launch_bounds__(GTHREADS, 6) void roi_gather_kernel(
    const float* __restrict__ rois,
    float* __restrict__ out)
{
    __shared__ float sout[CHALF * NBIN + 32];  // skewed: idx = c*49 + c/4 + bin
    __shared__ int   s_ylo[14], s_yhi[14], s_xlo[14], s_xhi[14];
    __shared__ float s_wy0[14], s_wy1[14], s_wx0[14], s_wx1[14];
    __shared__ int   s_off[NBIN * 16];   // combined corner offsets (in halves)
    __shared__ unsigned s_w[NBIN * 16];  // packed (w,w) half2 weights

    int n    = blockIdx.x;
    int half = blockIdx.y;
    int tid  = threadIdx.x;
    int warp = tid >> 5;
    int lane = tid & 31;

    const float* r = rois + n * 5;
    int   b  = (int)__ldg(r + 0);
    float sx = __ldg(r + 1) * 0.25f - 0.5f;
    float sy = __ldg(r + 2) * 0.25f - 0.5f;
    float ex = __ldg(r + 3) * 0.25f - 0.5f;
    float ey = __ldg(r + 4) * 0.25f - 0.5f;
    float bw = (ex - sx) / (float)OUTW;
    float bh = (ey - sy) / (float)OUTH;

    // --- stage 1: 14 y samples, 14 x samples ---
    if (tid < 14) {
        int s  = tid;
        int ph = s >> 1, iy = s & 1;
        float y = sy + ((float)ph + (0.25f + 0.5f * iy)) * bh;
        bool valid = (y > -1.0f) && (y < (float)H_);
        float y0 = fmaxf(y, 0.0f);
        int ylo = (int)floorf(y0);
        int yhi; float ly;
        if (ylo >= H_ - 1) { ylo = H_ - 1; yhi = H_ - 1; ly = 0.0f; }
        else               { yhi = ylo + 1; ly = y0 - (float)ylo; }
        s_ylo[s] = ylo * (W_ * C_);
        s_yhi[s] = yhi * (W_ * C_);
        s_wy0[s] = valid ? (1.0f - ly) * 0.25f : 0.0f;
        s_wy1[s] = valid ? ly * 0.25f : 0.0f;
    } else if (tid >= 64 && tid < 78) {
        int s  = tid - 64;
        int pw = s >> 1, ix = s & 1;
        float x = sx + ((float)pw + (0.25f + 0.5f * ix)) * bw;
        bool valid = (x > -1.0f) && (x < (float)W_);
        float x0 = fmaxf(x, 0.0f);
        int xlo = (int)floorf(x0);
        int xhi; float lx;
        if (xlo >= W_ - 1) { xlo = W_ - 1; xhi = W_ - 1; lx = 0.0f; }
        else               { xhi = xlo + 1; lx = x0 - (float)xlo; }
        s_xlo[s] = xlo * C_;
        s_xhi[s] = xhi * C_;
        s_wx0[s] = valid ? (1.0f - lx) : 0.0f;
        s_wx1[s] = valid ? lx : 0.0f;
    }
    __syncthreads();

    // --- stage 2: fused per-bin corner tables (49 bins x 16 entries) ---
    for (int e = tid; e < NBIN * 16; e += GTHREADS) {
        int bin = e >> 4;
        int j   = e & 15;
        int ph  = bin / OUTW;
        int pw  = bin - ph * OUTW;
        int iy = (j >> 3) & 1, ix = (j >> 2) & 1;
        int cy = (j >> 1) & 1, cx = j & 1;
        int syi = ph * 2 + iy;
        int sxi = pw * 2 + ix;
        int   yoff = cy ? s_yhi[syi] : s_ylo[syi];
        int   xoff = cx ? s_xhi[sxi] : s_xlo[sxi];
        float wy   = cy ? s_wy1[syi] : s_wy0[syi];
        float wx   = cx ? s_wx1[sxi] : s_wx0[sxi];
        __half2 h2 = __float2half2_rn(wy * wx);
        s_off[e] = yoff + xoff;
        s_w[e]   = *reinterpret_cast<unsigned*>(&h2);
    }
    __syncthreads();

    // lane -> 4 channels within this half
    int clane = lane * 4;
    const __half* fbase = g_feat16 + (size_t)b * HWC + half * CHALF + clane;

    #pragma unroll
    for (int it = 0; it < 7; it++) {
        int bin = warp + it * 7;
        const int*      off = s_off + (bin << 4);
        const unsigned* wp  = s_w   + (bin << 4);

        // 16 independent 8B loads, one front batch (MLP = 16)
        uint2 u[16];
        #pragma unroll
        for (int j = 0; j < 16; j++)
            u[j] = *(const uint2*)(fbase + off[j]);

        float a0 = 0.f, a1 = 0.f, a2 = 0.f, a3 = 0.f;

        #pragma unroll
        for (int s = 0; s < 4; s++) {
            __half2 hl = __floats2half2_rn(0.f, 0.f);
            __half2 hh = hl;
            #pragma unroll
            for (int c = 0; c < 4; c++) {
                int j = s * 4 + c;
                unsigned wraw = wp[j];
                __half2 w = *reinterpret_cast<__half2*>(&wraw);
                hl = __hfma2(w, *reinterpret_cast<__half2*>(&u[j].x), hl);
                hh = __hfma2(w, *reinterpret_cast<__half2*>(&u[j].y), hh);
            }
            float2 fl = __half22float2(hl);
            float2 fh = __half22float2(hh);
            a0 += fl.x; a1 += fl.y; a2 += fh.x; a3 += fh.y;
        }

        // skewed: idx = c*49 + c/4 + bin -> lane stride 197 (5 mod 32), conflict-free
        int base = clane * NBIN + (clane >> 2) + bin;
        sout[base]            = a0;
        sout[base + NBIN]     = a1;
        sout[base + 2 * NBIN] = a2;
        sout[base + 3 * NBIN] = a3;
    }
    __syncthreads();

    // coalesced writeout: this block owns out[n, half*128 : half*128+128, :, :]
    float* o = out + (size_t)n * (C_ * NBIN) + (size_t)half * CHALF * NBIN;
    for (int i = tid; i < CHALF * NBIN; i += GTHREADS) {
        int c = i / NBIN;
        o[i] = sout[i + (c >> 2)];
    }
}

extern "C" void kernel_launch(void* const* d_in, const int* in_sizes, int n_in,
                              void* d_out, int out_size)
{
    const float* feat = (const float*)d_in[0];
    const float* rois = (const float*)d_in[1];
    float* out = (float*)d_out;

    dim3 tgrid((W_ + 63) / 64, B_ * H_, C_ / 64);
    dim3 tblock(32, 8);
    transpose_kernel<<<tgrid, tblock>>>(feat);

    int n_rois = in_sizes[1] / 5;
    dim3 ggrid(n_rois, 2);
    roi_gather_kernel<<<ggrid, GTHREADS>>>(rois, out);
}

// round 15
// speedup vs baseline: 1.0308x; 1.0308x over previous
#include <cuda_runtime.h>
#include <cuda_fp16.h>

// RoIAlign: float2-read/STG.128-write transpose + champion r13 gather.
// feat: (B=2, C=256, H=200, W=336) fp32 NCHW
// rois: (N=1000, 5) [bidx, x1, y1, x2, y2] fp32
// out:  (N, 256, 7, 7) fp32

#define B_    2
#define C_    256
#define H_    200
#define W_    336
#define OUTH  7
#define OUTW  7
#define NBIN  49
#define HWC   (H_ * W_ * C_)
#define CHALF 128

// NHWC fp16 scratch: [B][H][W][C]
__device__ __half g_feat16[(size_t)B_ * HWC];

// ---------------------------------------------------------------------------
// Kernel 1: NCHW fp32 -> NHWC fp16. Block: 64 channels x 64 x-positions.
// Read: float2 (proven). Write: each thread packs 8 channels -> 1 STG.128;
// warp covers 4 x-positions x 64 channels = 4 x 128B coalesced transactions.
// ---------------------------------------------------------------------------
__global__ __launch_bounds__(256) void transpose_kernel(const float* __restrict__ feat)
{
    __shared__ float tile[64][65];   // [c][x]

    int xt = blockIdx.x * 64;
    int by = blockIdx.y;             // b*H + y
    int b  = by / H_;
    int y  = by % H_;
    int c0 = blockIdx.z * 64;
    int tx = threadIdx.x;
    int ty = threadIdx.y;
    int t  = ty * 32 + tx;

    const float* src = feat + ((size_t)(b * C_ + c0) * H_ + y) * W_;
    int  x2  = xt + 2 * tx;          // even
    bool xin = x2 < W_;              // W even -> covers x2+1 too

    #pragma unroll
    for (int k = 0; k < 8; k++) {
        int c = ty + k * 8;
        float2 v = make_float2(0.f, 0.f);
        if (xin) v = *(const float2*)(src + (size_t)c * (H_ * W_) + x2);
        tile[c][2 * tx]     = v.x;
        tile[c][2 * tx + 1] = v.y;
    }
    __syncthreads();

    // write phase: cl = (t&7)*8 channels, xl = (t>>3) + 32k x-positions
    int cl = (t & 7) * 8;
    __half* dst = g_feat16 + ((size_t)(b * H_ + y) * W_) * C_ + c0 + cl;

    #pragma unroll
    for (int k = 0; k < 2; k++) {
        int xl = (t >> 3) + k * 32;
        int x  = xt + xl;
        if (x < W_) {
            __half2 h0 = __floats2half2_rn(tile[cl + 0][xl], tile[cl + 1][xl]);
            __half2 h1 = __floats2half2_rn(tile[cl + 2][xl], tile[cl + 3][xl]);
            __half2 h2 = __floats2half2_rn(tile[cl + 4][xl], tile[cl + 5][xl]);
            __half2 h3 = __floats2half2_rn(tile[cl + 6][xl], tile[cl + 7][xl]);
            uint4 v;
            v.x = *reinterpret_cast<unsigned*>(&h0);
            v.y = *reinterpret_cast<unsigned*>(&h1);
            v.z = *reinterpret_cast<unsigned*>(&h2);
            v.w = *reinterpret_cast<unsigned*>(&h3);
            *reinterpret_cast<uint4*>(dst + (size_t)x * C_) = v;
        }
    }
}

// ---------------------------------------------------------------------------
// Kernel 2: gather (champion r13 config, byte-identical). grid (N, 2). 8 warps.
// One bin per warp per iteration; lane covers 4 channels (uint2) -> each
// corner is one contiguous 256B warp request. All 16 loads front-batched.
// ---------------------------------------------------------------------------
__global__ __launch_bounds__(256, 5) void roi_gather_kernel(
    const float* __restrict__ rois,
    float* __restrict__ out)
{
    __shared__ float sout[CHALF * NBIN + 32];  // skewed: idx = c*49 + c/4 + bin
    __shared__ int   s_ylo[14], s_yhi[14], s_xlo[14], s_xhi[14];
    __shared__ float s_wy0[14], s_wy1[14], s_wx0[14], s_wx1[14];
    __shared__ int   s_off[NBIN * 16];   // combined corner offsets (in halves)
    __shared__ unsigned s_w[NBIN * 16];  // packed (w,w) half2 weights

    int n    = blockIdx.x;
    int half = blockIdx.y;
    int tid  = threadIdx.x;
    int warp = tid >> 5;
    int lane = tid & 31;

    const float* r = rois + n * 5;
    int   b  = (int)__ldg(r + 0);
    float sx = __ldg(r + 1) * 0.25f - 0.5f;
    float sy = __ldg(r + 2) * 0.25f - 0.5f;
    float ex = __ldg(r + 3) * 0.25f - 0.5f;
    float ey = __ldg(r + 4) * 0.25f - 0.5f;
    float bw = (ex - sx) / (float)OUTW;
    float bh = (ey - sy) / (float)OUTH;

    // --- stage 1: 14 y samples, 14 x samples ---
    if (tid < 14) {
        int s  = tid;
        int ph = s >> 1, iy = s & 1;
        float y = sy + ((float)ph + (0.25f + 0.5f * iy)) * bh;
        bool valid = (y > -1.0f) && (y < (float)H_);
        float y0 = fmaxf(y, 0.0f);
        int ylo = (int)floorf(y0);
        int yhi; float ly;
        if (ylo >= H_ - 1) { ylo = H_ - 1; yhi = H_ - 1; ly = 0.0f; }
        else               { yhi = ylo + 1; ly = y0 - (float)ylo; }
        s_ylo[s] = ylo * (W_ * C_);
        s_yhi[s] = yhi * (W_ * C_);
        s_wy0[s] = valid ? (1.0f - ly) * 0.25f : 0.0f;
        s_wy1[s] = valid ? ly * 0.25f : 0.0f;
    } else if (tid >= 64 && tid < 78) {
        int s  = tid - 64;
        int pw = s >> 1, ix = s & 1;
        float x = sx + ((float)pw + (0.25f + 0.5f * ix)) * bw;
        bool valid = (x > -1.0f) && (x < (float)W_);
        float x0 = fmaxf(x, 0.0f);
        int xlo = (int)floorf(x0);
        int xhi; float lx;
        if (xlo >= W_ - 1) { xlo = W_ - 1; xhi = W_ - 1; lx = 0.0f; }
        else               { xhi = xlo + 1; lx = x0 - (float)xlo; }
        s_xlo[s] = xlo * C_;
        s_xhi[s] = xhi * C_;
        s_wx0[s] = valid ? (1.0f - lx) : 0.0f;
        s_wx1[s] = valid ? lx : 0.0f;
    }
    __syncthreads();

    // --- stage 2: fused per-bin corner tables (49 bins x 16 entries) ---
    for (int e = tid; e < NBIN * 16; e += 256) {
        int bin = e >> 4;
        int j   = e & 15;
        int ph  = bin / OUTW;
        int pw  = bin - ph * OUTW;
        int iy = (j >> 3) & 1, ix = (j >> 2) & 1;
        int cy = (j >> 1) & 1, cx = j & 1;
        int syi = ph * 2 + iy;
        int sxi = pw * 2 + ix;
        int   yoff = cy ? s_yhi[syi] : s_ylo[syi];
        int   xoff = cx ? s_xhi[sxi] : s_xlo[sxi];
        float wy   = cy ? s_wy1[syi] : s_wy0[syi];
        float wx   = cx ? s_wx1[sxi] : s_wx0[sxi];
        __half2 h2 = __float2half2_rn(wy * wx);
        s_off[e] = yoff + xoff;
        s_w[e]   = *reinterpret_cast<unsigned*>(&h2);
    }
    __syncthreads();

    // lane -> 4 channels within this half
    int clane = lane * 4;
    const __half* fbase = g_feat16 + (size_t)b * HWC + half * CHALF + clane;

    for (int bin = warp; bin < NBIN; bin += 8) {
        const int*      off = s_off + (bin << 4);
        const unsigned* wp  = s_w   + (bin << 4);

        // 16 independent 8B loads, one front batch (MLP = 16)
        uint2 u[16];
        #pragma unroll
        for (int j = 0; j < 16; j++)
            u[j] = *(const uint2*)(fbase + off[j]);

        float a0 = 0.f, a1 = 0.f, a2 = 0.f, a3 = 0.f;

        #pragma unroll
        for (int s = 0; s < 4; s++) {
            __half2 hl = __floats2half2_rn(0.f, 0.f);
            __half2 hh = hl;
            #pragma unroll
            for (int c = 0; c < 4; c++) {
                int j = s * 4 + c;
                unsigned wraw = wp[j];
                __half2 w = *reinterpret_cast<__half2*>(&wraw);
                hl = __hfma2(w, *reinterpret_cast<__half2*>(&u[j].x), hl);
                hh = __hfma2(w, *reinterpret_cast<__half2*>(&u[j].y), hh);
            }
            float2 fl = __half22float2(hl);
            float2 fh = __half22float2(hh);
            a0 += fl.x; a1 += fl.y; a2 += fh.x; a3 += fh.y;
        }

        // skewed: idx = c*49 + c/4 + bin -> lane stride 197 (5 mod 32), conflict-free
        int base = clane * NBIN + (clane >> 2) + bin;
        sout[base]            = a0;
        sout[base + NBIN]     = a1;
        sout[base + 2 * NBIN] = a2;
        sout[base + 3 * NBIN] = a3;
    }
    __syncthreads();

    // coalesced writeout: this block owns out[n, half*128 : half*128+128, :, :]
    float* o = out + (size_t)n * (C_ * NBIN) + (size_t)half * CHALF * NBIN;
    #pragma unroll 7
    for (int i = tid; i < CHALF * NBIN; i += 256) {
        int c = i / NBIN;
        o[i] = sout[i + (c >> 2)];
    }
}

extern "C" void kernel_launch(void* const* d_in, const int* in_sizes, int n_in,
                              void* d_out, int out_size)
{
    const float* feat = (const float*)d_in[0];
    const float* rois = (const float*)d_in[1];
    float* out = (float*)d_out;

    dim3 tgrid((W_ + 63) / 64, B_ * H_, C_ / 64);
    dim3 tblock(32, 8);
    transpose_kernel<<<tgrid, tblock>>>(feat);

    int n_rois = in_sizes[1] / 5;
    dim3 ggrid(n_rois, 2);
    roi_gather_kernel<<<ggrid, 256>>>(rois, out);
}